// round 10
// baseline (speedup 1.0000x reference)
#include <cuda_runtime.h>
#include <cstdint>

// x:      (2, 64, 32, 32, 32) fp32
// weight: (64, 32, 3, 3, 3)   fp32
// bias:   (32,)               fp32
// out:    (2, 32, 66, 66, 66) fp32
//
// Core: out[n,co,2z+1] = bias[co] + sum_{ci,tap} W[ci,co,26-tap]*x[n,ci,z-1+k]
// All other outputs bias-only. Conv CTAs write all of [0,64)^3 (2x2x2 cubes);
// prep kernel fills border slabs (any coord >= 64) + flips weights.

#define OUT_S 66
#define PLANE 4356            // 66*66
#define CH_STRIDE 287496      // 66^3
#define CIC 8
#define NCHUNK 8

// x halo in smem: [ci][dd(10)][104 words] (plane = hh*10+ww in [0,100), 4 pad)
// stride 104 mod 32 == 8 -> lanes (ldq*8+lw) hit 32 distinct banks.
#define XPLANE 104
#define XCI (10 * XPLANE)          // 1040 words per ci
#define XS_BYTES (CIC * XCI * 4)   // 33280
#define WS_BYTES (CIC * 27 * 32 * 4) // 27648
#define BUF_BYTES (XS_BYTES + WS_BYTES) // 60928
#define SM_TOTAL (2 * BUF_BYTES)   // 121856

__device__ __align__(16) float g_wflip[64 * 27 * 32];

#define WPREP_BLOCKS 216
#define DHROW_BLOCKS 2080
#define WPAIR_BLOCKS 1024
#define PREP_BLOCKS (WPREP_BLOCKS + DHROW_BLOCKS + WPAIR_BLOCKS)

// ---------------------------------------------------------------------------
__global__ void prep_kernel(const float* __restrict__ w,
                            const float* __restrict__ bias,
                            float* __restrict__ out) {
    const int b   = blockIdx.x;
    const int tid = threadIdx.x;
    if (b < WPREP_BLOCKS) {
        int i = b * 256 + tid;
        if (i < 55296) {
            int ci = i / 864;
            int r  = i - ci * 864;
            int k  = r >> 5;
            int co = r & 31;
            g_wflip[i] = w[(ci * 32 + co) * 27 + (26 - k)];
        }
    } else if (b < WPREP_BLOCKS + DHROW_BLOCKS) {
        int wg   = (b - WPREP_BLOCKS) * 8 + (tid >> 5);
        int lane = tid & 31;
        int ch = wg / 260;
        int r  = wg - ch * 260;
        int d, h;
        if (r < 132) { d = 64 + (r >= 66 ? 1 : 0); h = r - (r >= 66 ? 66 : 0); }
        else         { int r2 = r - 132; d = r2 >> 1; h = 64 + (r2 & 1); }
        float bv = __ldg(&bias[ch & 31]);
        float* row = out + (size_t)ch * CH_STRIDE + (size_t)d * PLANE + h * OUT_S;
        for (int i = lane; i < OUT_S; i += 32) row[i] = bv;
    } else {
        int idx = (b - WPREP_BLOCKS - DHROW_BLOCKS) * 256 + tid;
        int ch  = idx >> 12;
        int rem = idx & 4095;
        int d   = rem >> 6;
        int h   = rem & 63;
        float bv = __ldg(&bias[ch & 31]);
        float2* p = (float2*)(out + (size_t)ch * CH_STRIDE
                              + (size_t)d * PLANE + h * OUT_S + 64);
        *p = make_float2(bv, bv);
    }
}

// ---------------------------------------------------------------------------
__device__ __forceinline__ void cp4_zfill(uint32_t saddr, const float* g, int ok) {
    asm volatile("cp.async.ca.shared.global [%0], [%1], 4, %2;"
                 :: "r"(saddr), "l"(g), "r"(ok ? 4 : 0) : "memory");
}
__device__ __forceinline__ void cp16(uint32_t saddr, const float4* g) {
    asm volatile("cp.async.cg.shared.global [%0], [%1], 16;"
                 :: "r"(saddr), "l"(g) : "memory");
}
__device__ __forceinline__ void cp_commit() {
    asm volatile("cp.async.commit_group;" ::: "memory");
}
template <int N>
__device__ __forceinline__ void cp_wait() {
    asm volatile("cp.async.wait_group %0;" :: "n"(N) : "memory");
}

// ---------------------------------------------------------------------------
// 512 threads: lw = tid&7, ldq = (tid>>3)&3, lh = (tid>>5)&7, coh = tid>>8.
//   lane = ldq*8+lw -> x LDS conflict-free (plane stride 104 == 8 mod 32)
//   lh, coh warp-uniform -> weight LDS.128 broadcast
// Thread owns points zloc = ldq + 4p (p<2) at (zh0+lh, zw0+lw), 16 co.
// Per (ci,kh,kw): 6 LDS.32 + 6 mov + 12 LDS.128 + 48 fma.rn.f32x2.
// Grid (4,4,8) = 128 CTAs, one per SM. cp.async double-buffered.
// ---------------------------------------------------------------------------
__global__ void __launch_bounds__(512, 1)
conv_core_kernel(const float* __restrict__ x,
                 const float* __restrict__ bias,
                 float* __restrict__ out) {
    extern __shared__ __align__(16) char smem[];
    uint32_t sb;
    asm("{ .reg .u64 t; cvta.to.shared.u64 t, %1; cvt.u32.u64 %0, t; }"
        : "=r"(sb) : "l"(smem));

    const int tid = threadIdx.x;
    const int lw  = tid & 7;
    const int ldq = (tid >> 3) & 3;
    const int lh  = (tid >> 5) & 7;
    const int coh = tid >> 8;                 // 0/1 -> co base 16*coh

    const int tw = blockIdx.x, th = blockIdx.y;
    const int nz = blockIdx.z;
    const int n  = nz >> 2;
    const int td = nz & 3;
    const int zd0 = td * 8, zh0 = th * 8, zw0 = tw * 8;

    const float* xn = x + (size_t)n * (64 * 32768);

    auto issue_chunk = [&](int cc, int buf) {
        uint32_t sx = sb + buf * BUF_BYTES;
#pragma unroll
        for (int j = 0; j < 16; ++j) {
            int i = tid + j * 512;
            if (i < 8000) {
                int ci = i / 1000;
                int r  = i - ci * 1000;
                int dd = r / 100;
                int pp = r - dd * 100;          // hh*10+ww
                int hh = pp / 10;
                int ww = pp - hh * 10;
                int gd = zd0 - 1 + dd;
                int gh = zh0 - 1 + hh;
                int gw = zw0 - 1 + ww;
                int ok = (gd >= 0 && gd < 32 && gh >= 0 && gh < 32 &&
                          gw >= 0 && gw < 32);
                const float* g = xn + (((size_t)(cc * CIC + ci) * 32 + (gd & 31))
                                       * 32 + (gh & 31)) * 32 + (gw & 31);
                cp4_zfill(sx + (ci * XCI + dd * XPLANE + pp) * 4, g, ok);
            }
        }
        uint32_t sw = sx + XS_BYTES;
        const float4* gw4 = (const float4*)(g_wflip + cc * 6912);
#pragma unroll
        for (int j = 0; j < 4; ++j) {
            int i = tid + j * 512;
            if (i < 1728) cp16(sw + i * 16, gw4 + i);
        }
        cp_commit();
    };

    // acc[p][j] = point p (zloc = ldq+4p), co pair {16coh+2j, 16coh+2j+1}
    unsigned long long acc[2][8];
#pragma unroll
    for (int p = 0; p < 2; ++p)
#pragma unroll
        for (int j = 0; j < 8; ++j) acc[p][j] = 0ull;

    issue_chunk(0, 0);

#pragma unroll 1
    for (int cc = 0; cc < NCHUNK; ++cc) {
        const int buf = cc & 1;
        if (cc + 1 < NCHUNK) {
            issue_chunk(cc + 1, buf ^ 1);
            cp_wait<1>();
        } else {
            cp_wait<0>();
        }
        __syncthreads();

        const float* xsb = (const float*)(smem + buf * BUF_BYTES);
        const float* wsb = (const float*)(smem + buf * BUF_BYTES + XS_BYTES);

#pragma unroll 1
        for (int ci = 0; ci < CIC; ++ci) {
            // base: dd = ldq, hh = lh, ww = lw
            const float* xci = xsb + ci * XCI + ldq * XPLANE + lh * 10 + lw;
            const float* wb  = wsb + ci * 864 + coh * 16;
#pragma unroll 1
            for (int kh = 0; kh < 3; ++kh) {
#pragma unroll 1
                for (int kw = 0; kw < 3; ++kw) {
                    const float* xr = xci + kh * 10 + kw;
                    // 6 d-planes: dd = ldq + {0,1,2,4,5,6}
                    unsigned long long xq2[2][3];
#pragma unroll
                    for (int p = 0; p < 2; ++p)
#pragma unroll
                    for (int kd = 0; kd < 3; ++kd) {
                        float xv = xr[(4 * p + kd) * XPLANE];
                        asm("mov.b64 %0, {%1, %1};"
                            : "=l"(xq2[p][kd]) : "f"(xv));
                    }
#pragma unroll
                    for (int kd = 0; kd < 3; ++kd) {
                        const ulonglong2* wr = (const ulonglong2*)
                            (wb + (kd * 9 + kh * 3 + kw) * 32);
                        ulonglong2 w0 = wr[0];   // co 16coh..+3 (broadcast)
                        ulonglong2 w1 = wr[1];   // +4..+7
                        ulonglong2 w2 = wr[2];   // +8..+11
                        ulonglong2 w3 = wr[3];   // +12..+15
#pragma unroll
                        for (int p = 0; p < 2; ++p) {
                            unsigned long long xv2 = xq2[p][kd];
                            asm("fma.rn.f32x2 %0, %1, %2, %0;"
                                : "+l"(acc[p][0]) : "l"(xv2), "l"(w0.x));
                            asm("fma.rn.f32x2 %0, %1, %2, %0;"
                                : "+l"(acc[p][1]) : "l"(xv2), "l"(w0.y));
                            asm("fma.rn.f32x2 %0, %1, %2, %0;"
                                : "+l"(acc[p][2]) : "l"(xv2), "l"(w1.x));
                            asm("fma.rn.f32x2 %0, %1, %2, %0;"
                                : "+l"(acc[p][3]) : "l"(xv2), "l"(w1.y));
                            asm("fma.rn.f32x2 %0, %1, %2, %0;"
                                : "+l"(acc[p][4]) : "l"(xv2), "l"(w2.x));
                            asm("fma.rn.f32x2 %0, %1, %2, %0;"
                                : "+l"(acc[p][5]) : "l"(xv2), "l"(w2.y));
                            asm("fma.rn.f32x2 %0, %1, %2, %0;"
                                : "+l"(acc[p][6]) : "l"(xv2), "l"(w3.x));
                            asm("fma.rn.f32x2 %0, %1, %2, %0;"
                                : "+l"(acc[p][7]) : "l"(xv2), "l"(w3.y));
                        }
                    }
                }
            }
        }
        __syncthreads();
    }

    // ---- epilogue: full 2x2x2 cubes (7 bias + 1 core per point/co) ----
    float bv[16];
#pragma unroll
    for (int j = 0; j < 16; ++j) bv[j] = __ldg(&bias[coh * 16 + j]);

    const int ohe = 2 * (zh0 + lh);
    const int owe = 2 * (zw0 + lw);
#pragma unroll
    for (int p = 0; p < 2; ++p) {
        const int od = 2 * (zd0 + ldq + 4 * p);
#pragma unroll
        for (int j = 0; j < 8; ++j) {
            float2 v;
            asm("mov.b64 {%0, %1}, %2;" : "=f"(v.x), "=f"(v.y)
                                        : "l"(acc[p][j]));
#pragma unroll
            for (int s = 0; s < 2; ++s) {
                const int co = coh * 16 + 2 * j + s;
                const float b  = bv[2 * j + s];
                const float cr = (s == 0 ? v.x : v.y) + b;
                float* base = out + (size_t)(n * 32 + co) * CH_STRIDE
                            + (size_t)od * PLANE + ohe * OUT_S + owe;
                float2 bb = make_float2(b, b);
                float2 bc = make_float2(b, cr);
                *(float2*)(base)                 = bb;
                *(float2*)(base + OUT_S)         = bb;
                *(float2*)(base + PLANE)         = bb;
                *(float2*)(base + PLANE + OUT_S) = bc;
            }
        }
    }
}

// ---------------------------------------------------------------------------
extern "C" void kernel_launch(void* const* d_in, const int* in_sizes, int n_in,
                              void* d_out, int out_size) {
    const float* x = nullptr;
    const float* w = nullptr;
    const float* b = nullptr;
    for (int i = 0; i < n_in; ++i) {
        if (in_sizes[i] == 4194304)    x = (const float*)d_in[i];
        else if (in_sizes[i] == 55296) w = (const float*)d_in[i];
        else if (in_sizes[i] == 32)    b = (const float*)d_in[i];
    }
    float* out = (float*)d_out;

    cudaFuncSetAttribute(conv_core_kernel,
                         cudaFuncAttributeMaxDynamicSharedMemorySize, SM_TOTAL);

    prep_kernel<<<PREP_BLOCKS, 256>>>(w, b, out);

    dim3 grid(4, 4, 8);   // 128 CTAs = one per SM, single wave
    conv_core_kernel<<<grid, 512, SM_TOTAL>>>(x, b, out);
}

// round 11
// speedup vs baseline: 1.2338x; 1.2338x over previous
#include <cuda_runtime.h>
#include <cstdint>

// x:      (2, 64, 32, 32, 32) fp32
// weight: (64, 32, 3, 3, 3)   fp32
// bias:   (32,)               fp32
// out:    (2, 32, 66, 66, 66) fp32
//
// Core: out[n,co,2z+1] = bias[co] + sum_{ci,tap} W[ci,co,26-tap]*x[n,ci,z-1+k]
// All other outputs bias-only. Conv CTAs write all of [0,64)^3 (2x2x2 cubes);
// prep kernel fills border slabs (any coord >= 64) + flips weights.

#define OUT_S 66
#define PLANE 4356            // 66*66
#define CH_STRIDE 287496      // 66^3
#define CIC 8
#define NCHUNK 8

// per-buffer smem: xs 8*10*10*10 floats = 32000 B, ws 8*27*32 = 27648 B
#define XS_BYTES 32000
#define BUF_BYTES 59648
#define SM_TOTAL (2 * BUF_BYTES)   // 119296

__device__ __align__(16) float g_wflip[64 * 27 * 32];

#define WPREP_BLOCKS 216
#define DHROW_BLOCKS 2080
#define WPAIR_BLOCKS 1024
#define PREP_BLOCKS (WPREP_BLOCKS + DHROW_BLOCKS + WPAIR_BLOCKS)

// ---------------------------------------------------------------------------
__global__ void prep_kernel(const float* __restrict__ w,
                            const float* __restrict__ bias,
                            float* __restrict__ out) {
    const int b   = blockIdx.x;
    const int tid = threadIdx.x;
    if (b < WPREP_BLOCKS) {
        int i = b * 256 + tid;
        if (i < 55296) {
            int ci = i / 864;
            int r  = i - ci * 864;
            int k  = r >> 5;
            int co = r & 31;
            g_wflip[i] = w[(ci * 32 + co) * 27 + (26 - k)];
        }
    } else if (b < WPREP_BLOCKS + DHROW_BLOCKS) {
        int wg   = (b - WPREP_BLOCKS) * 8 + (tid >> 5);
        int lane = tid & 31;
        int ch = wg / 260;
        int r  = wg - ch * 260;
        int d, h;
        if (r < 132) { d = 64 + (r >= 66 ? 1 : 0); h = r - (r >= 66 ? 66 : 0); }
        else         { int r2 = r - 132; d = r2 >> 1; h = 64 + (r2 & 1); }
        float bv = __ldg(&bias[ch & 31]);
        float* row = out + (size_t)ch * CH_STRIDE + (size_t)d * PLANE + h * OUT_S;
        for (int i = lane; i < OUT_S; i += 32) row[i] = bv;
    } else {
        int idx = (b - WPREP_BLOCKS - DHROW_BLOCKS) * 256 + tid;
        int ch  = idx >> 12;
        int rem = idx & 4095;
        int d   = rem >> 6;
        int h   = rem & 63;
        float bv = __ldg(&bias[ch & 31]);
        float2* p = (float2*)(out + (size_t)ch * CH_STRIDE
                              + (size_t)d * PLANE + h * OUT_S + 64);
        *p = make_float2(bv, bv);
    }
}

// ---------------------------------------------------------------------------
__device__ __forceinline__ void cp4_zfill(uint32_t saddr, const float* g, int ok) {
    asm volatile("cp.async.ca.shared.global [%0], [%1], 4, %2;"
                 :: "r"(saddr), "l"(g), "r"(ok ? 4 : 0) : "memory");
}
__device__ __forceinline__ void cp16(uint32_t saddr, const float4* g) {
    asm volatile("cp.async.cg.shared.global [%0], [%1], 16;"
                 :: "r"(saddr), "l"(g) : "memory");
}
__device__ __forceinline__ void cp_commit() {
    asm volatile("cp.async.commit_group;" ::: "memory");
}
template <int N>
__device__ __forceinline__ void cp_wait() {
    asm volatile("cp.async.wait_group %0;" :: "n"(N) : "memory");
}

// ---------------------------------------------------------------------------
// Block = 1024 threads, (8,8,8) z-tile:
//   lw = tid&7, lh = (tid>>3)&7, ldd = (tid>>6)&3, coh = (tid>>8)&3
// Thread owns 2 points zloc = ldd + 4p (p<2) at (zh0+lh, zw0+lw), 8 co
// (co base 8*coh). 32 warps/CTA = 8 per SMSP for latency coverage.
// Per (ci,kh,kw) window: 6 LDS.32 + 6 mov + 6 LDS.128 (broadcast) + 24 fma.f32x2.
// Grid (4,4,8) = 128 CTAs, one per SM, single wave. cp.async double-buffered.
// ---------------------------------------------------------------------------
__global__ void __launch_bounds__(1024, 1)
conv_core_kernel(const float* __restrict__ x,
                 const float* __restrict__ bias,
                 float* __restrict__ out) {
    extern __shared__ __align__(16) char smem[];
    uint32_t sb;
    asm("{ .reg .u64 t; cvta.to.shared.u64 t, %1; cvt.u32.u64 %0, t; }"
        : "=r"(sb) : "l"(smem));

    const int tid = threadIdx.x;
    const int lw  = tid & 7;
    const int lh  = (tid >> 3) & 7;
    const int ldd = (tid >> 6) & 3;
    const int coh = (tid >> 8) & 3;           // co base 8*coh

    const int tw = blockIdx.x, th = blockIdx.y;
    const int nz = blockIdx.z;
    const int n  = nz >> 2;
    const int td = nz & 3;
    const int zd0 = td * 8, zh0 = th * 8, zw0 = tw * 8;

    const float* xn = x + (size_t)n * (64 * 32768);

    auto issue_chunk = [&](int cc, int buf) {
        uint32_t sx = sb + buf * BUF_BYTES;
#pragma unroll
        for (int j = 0; j < 8; ++j) {
            int i = tid + j * 1024;
            if (i < 8000) {
                int ci = i / 1000;
                int r  = i - ci * 1000;
                int dd = r / 100;
                int r2 = r - dd * 100;
                int hh = r2 / 10;
                int ww = r2 - hh * 10;
                int gd = zd0 - 1 + dd;
                int gh = zh0 - 1 + hh;
                int gw = zw0 - 1 + ww;
                int ok = (gd >= 0 && gd < 32 && gh >= 0 && gh < 32 &&
                          gw >= 0 && gw < 32);
                const float* g = xn + (((size_t)(cc * CIC + ci) * 32 + (gd & 31))
                                       * 32 + (gh & 31)) * 32 + (gw & 31);
                cp4_zfill(sx + i * 4, g, ok);
            }
        }
        uint32_t sw = sx + XS_BYTES;
        const float4* gw4 = (const float4*)(g_wflip + cc * 6912);
#pragma unroll
        for (int j = 0; j < 2; ++j) {
            int i = tid + j * 1024;
            if (i < 1728) cp16(sw + i * 16, gw4 + i);
        }
        cp_commit();
    };

    // acc[p][j] = point p (zloc = ldd + 4p), co pair {8coh+2j, 8coh+2j+1}
    unsigned long long acc[2][4];
#pragma unroll
    for (int p = 0; p < 2; ++p)
#pragma unroll
        for (int j = 0; j < 4; ++j) acc[p][j] = 0ull;

    issue_chunk(0, 0);

#pragma unroll 1
    for (int cc = 0; cc < NCHUNK; ++cc) {
        const int buf = cc & 1;
        if (cc + 1 < NCHUNK) {
            issue_chunk(cc + 1, buf ^ 1);
            cp_wait<1>();
        } else {
            cp_wait<0>();
        }
        __syncthreads();

        const float* xsb = (const float*)(smem + buf * BUF_BYTES);
        const float* wsb = (const float*)(smem + buf * BUF_BYTES + XS_BYTES);

#pragma unroll 1
        for (int ci = 0; ci < CIC; ++ci) {
            const float* xci = xsb + ci * 1000 + ldd * 100 + lh * 10 + lw;
            const float* wb  = wsb + ci * 864 + coh * 8;
#pragma unroll 1
            for (int kh = 0; kh < 3; ++kh) {
#pragma unroll 1
                for (int kw = 0; kw < 3; ++kw) {
                    const float* xr = xci + kh * 10 + kw;
                    // 6 d-planes: dd = ldd + 4p + kd
                    unsigned long long xq2[2][3];
#pragma unroll
                    for (int p = 0; p < 2; ++p)
#pragma unroll
                    for (int kd = 0; kd < 3; ++kd) {
                        float xv = xr[(4 * p + kd) * 100];
                        asm("mov.b64 %0, {%1, %1};"
                            : "=l"(xq2[p][kd]) : "f"(xv));
                    }
#pragma unroll
                    for (int kd = 0; kd < 3; ++kd) {
                        const ulonglong2* wr = (const ulonglong2*)
                            (wb + (kd * 9 + kh * 3 + kw) * 32);
                        ulonglong2 w0 = wr[0];   // co 8coh..+3 (broadcast)
                        ulonglong2 w1 = wr[1];   // co 8coh+4..+7
#pragma unroll
                        for (int p = 0; p < 2; ++p) {
                            unsigned long long xv2 = xq2[p][kd];
                            asm("fma.rn.f32x2 %0, %1, %2, %0;"
                                : "+l"(acc[p][0]) : "l"(xv2), "l"(w0.x));
                            asm("fma.rn.f32x2 %0, %1, %2, %0;"
                                : "+l"(acc[p][1]) : "l"(xv2), "l"(w0.y));
                            asm("fma.rn.f32x2 %0, %1, %2, %0;"
                                : "+l"(acc[p][2]) : "l"(xv2), "l"(w1.x));
                            asm("fma.rn.f32x2 %0, %1, %2, %0;"
                                : "+l"(acc[p][3]) : "l"(xv2), "l"(w1.y));
                        }
                    }
                }
            }
        }
        __syncthreads();
    }

    // ---- epilogue: full 2x2x2 cubes (7 bias + 1 core per point/co) ----
    float bv[8];
#pragma unroll
    for (int j = 0; j < 8; ++j) bv[j] = __ldg(&bias[coh * 8 + j]);

    const int ohe = 2 * (zh0 + lh);
    const int owe = 2 * (zw0 + lw);
#pragma unroll
    for (int p = 0; p < 2; ++p) {
        const int od = 2 * (zd0 + ldd + 4 * p);
#pragma unroll
        for (int j = 0; j < 4; ++j) {
            float2 v;
            asm("mov.b64 {%0, %1}, %2;" : "=f"(v.x), "=f"(v.y)
                                        : "l"(acc[p][j]));
#pragma unroll
            for (int s = 0; s < 2; ++s) {
                const int co = coh * 8 + 2 * j + s;
                const float b  = bv[2 * j + s];
                const float cr = (s == 0 ? v.x : v.y) + b;
                float* base = out + (size_t)(n * 32 + co) * CH_STRIDE
                            + (size_t)od * PLANE + ohe * OUT_S + owe;
                float2 bb = make_float2(b, b);
                float2 bc = make_float2(b, cr);
                *(float2*)(base)                 = bb;
                *(float2*)(base + OUT_S)         = bb;
                *(float2*)(base + PLANE)         = bb;
                *(float2*)(base + PLANE + OUT_S) = bc;
            }
        }
    }
}

// ---------------------------------------------------------------------------
extern "C" void kernel_launch(void* const* d_in, const int* in_sizes, int n_in,
                              void* d_out, int out_size) {
    const float* x = nullptr;
    const float* w = nullptr;
    const float* b = nullptr;
    for (int i = 0; i < n_in; ++i) {
        if (in_sizes[i] == 4194304)    x = (const float*)d_in[i];
        else if (in_sizes[i] == 55296) w = (const float*)d_in[i];
        else if (in_sizes[i] == 32)    b = (const float*)d_in[i];
    }
    float* out = (float*)d_out;

    cudaFuncSetAttribute(conv_core_kernel,
                         cudaFuncAttributeMaxDynamicSharedMemorySize, SM_TOTAL);

    prep_kernel<<<PREP_BLOCKS, 256>>>(w, b, out);

    dim3 grid(4, 4, 8);   // 128 CTAs = one per SM, single wave
    conv_core_kernel<<<grid, 1024, SM_TOTAL>>>(x, b, out);
}

// round 12
// speedup vs baseline: 1.6972x; 1.3756x over previous
#include <cuda_runtime.h>
#include <cstdint>

// x:      (2, 64, 32, 32, 32) fp32
// weight: (64, 32, 3, 3, 3)   fp32
// bias:   (32,)               fp32
// out:    (2, 32, 66, 66, 66) fp32
//
// Core: out[n,co,2z+1] = bias[co] + sum_{ci,tap} W[ci,co,26-tap]*x[n,ci,z-1+k]
// All other outputs bias-only. Conv CTAs write all of [0,64)^3 (2x2x2 cubes);
// prep kernel fills border slabs (any coord >= 64) + flips weights.

#define OUT_S 66
#define PLANE 4356            // 66*66
#define CH_STRIDE 287496      // 66^3
#define CIC 8
#define NCHUNK 8

// per-buffer smem: xs 8*10*10*10 floats = 32000 B, ws 8*27*32 = 27648 B
#define XS_BYTES 32000
#define BUF_BYTES 59648
#define SM_TOTAL (2 * BUF_BYTES)   // 119296

__device__ __align__(16) float g_wflip[64 * 27 * 32];

#define WPREP_BLOCKS 216
#define DHROW_BLOCKS 2080
#define WPAIR_BLOCKS 1024
#define PREP_BLOCKS (WPREP_BLOCKS + DHROW_BLOCKS + WPAIR_BLOCKS)

// ---------------------------------------------------------------------------
__global__ void prep_kernel(const float* __restrict__ w,
                            const float* __restrict__ bias,
                            float* __restrict__ out) {
    const int b   = blockIdx.x;
    const int tid = threadIdx.x;
    if (b < WPREP_BLOCKS) {
        int i = b * 256 + tid;
        if (i < 55296) {
            int ci = i / 864;
            int r  = i - ci * 864;
            int k  = r >> 5;
            int co = r & 31;
            g_wflip[i] = w[(ci * 32 + co) * 27 + (26 - k)];
        }
    } else if (b < WPREP_BLOCKS + DHROW_BLOCKS) {
        int wg   = (b - WPREP_BLOCKS) * 8 + (tid >> 5);
        int lane = tid & 31;
        int ch = wg / 260;
        int r  = wg - ch * 260;
        int d, h;
        if (r < 132) { d = 64 + (r >= 66 ? 1 : 0); h = r - (r >= 66 ? 66 : 0); }
        else         { int r2 = r - 132; d = r2 >> 1; h = 64 + (r2 & 1); }
        float bv = __ldg(&bias[ch & 31]);
        float* row = out + (size_t)ch * CH_STRIDE + (size_t)d * PLANE + h * OUT_S;
        for (int i = lane; i < OUT_S; i += 32) row[i] = bv;
    } else {
        int idx = (b - WPREP_BLOCKS - DHROW_BLOCKS) * 256 + tid;
        int ch  = idx >> 12;
        int rem = idx & 4095;
        int d   = rem >> 6;
        int h   = rem & 63;
        float bv = __ldg(&bias[ch & 31]);
        float2* p = (float2*)(out + (size_t)ch * CH_STRIDE
                              + (size_t)d * PLANE + h * OUT_S + 64);
        *p = make_float2(bv, bv);
    }
}

// ---------------------------------------------------------------------------
__device__ __forceinline__ void cp4_zfill(uint32_t saddr, const float* g, int ok) {
    asm volatile("cp.async.ca.shared.global [%0], [%1], 4, %2;"
                 :: "r"(saddr), "l"(g), "r"(ok ? 4 : 0) : "memory");
}
__device__ __forceinline__ void cp16(uint32_t saddr, const float4* g) {
    asm volatile("cp.async.cg.shared.global [%0], [%1], 16;"
                 :: "r"(saddr), "l"(g) : "memory");
}
__device__ __forceinline__ void cp_commit() {
    asm volatile("cp.async.commit_group;" ::: "memory");
}
template <int N>
__device__ __forceinline__ void cp_wait() {
    asm volatile("cp.async.wait_group %0;" :: "n"(N) : "memory");
}

// ---------------------------------------------------------------------------
// Block = 512 threads, (8,8,8) z-tile. Thread decode:
//   wq = tid&3, hq = (tid>>2)&3, dq0 = (tid>>4)&1   (lane bits)
//   dq1 = (tid>>5)&1, cog = (tid>>6)&7              (warp-uniform)
//   dq = dq0 | (dq1<<1)
// Thread owns a 2x2x2 point block at (zd0+2dq, zh0+2hq, zw0+2wq), 4 co
// (base cog*4). Per ci: 4 halo d-planes of 16 x values (8 LDS.64 each,
// reused across taps), 54 broadcast LDS.128 weights, 432 fma.rn.f32x2.
// Grid (4,4,8) = 128 CTAs, one per SM, single wave. cp.async double-buffered.
// ---------------------------------------------------------------------------
__global__ void __launch_bounds__(512, 1)
conv_core_kernel(const float* __restrict__ x,
                 const float* __restrict__ bias,
                 float* __restrict__ out) {
    extern __shared__ __align__(16) char smem[];
    uint32_t sb;
    asm("{ .reg .u64 t; cvta.to.shared.u64 t, %1; cvt.u32.u64 %0, t; }"
        : "=r"(sb) : "l"(smem));

    const int tid = threadIdx.x;
    const int wq  = tid & 3;
    const int hq  = (tid >> 2) & 3;
    const int dq  = ((tid >> 4) & 1) | (((tid >> 5) & 1) << 1);
    const int cog = (tid >> 6) & 7;           // co base 4*cog

    const int tw = blockIdx.x, th = blockIdx.y;
    const int nz = blockIdx.z;
    const int n  = nz >> 2;
    const int td = nz & 3;
    const int zd0 = td * 8, zh0 = th * 8, zw0 = tw * 8;

    const float* xn = x + (size_t)n * (64 * 32768);

    auto issue_chunk = [&](int cc, int buf) {
        uint32_t sx = sb + buf * BUF_BYTES;
#pragma unroll
        for (int j = 0; j < 16; ++j) {
            int i = tid + j * 512;
            if (i < 8000) {
                int ci = i / 1000;
                int r  = i - ci * 1000;
                int dd = r / 100;
                int r2 = r - dd * 100;
                int hh = r2 / 10;
                int ww = r2 - hh * 10;
                int gd = zd0 - 1 + dd;
                int gh = zh0 - 1 + hh;
                int gw = zw0 - 1 + ww;
                int ok = (gd >= 0 && gd < 32 && gh >= 0 && gh < 32 &&
                          gw >= 0 && gw < 32);
                const float* g = xn + (((size_t)(cc * CIC + ci) * 32 + (gd & 31))
                                       * 32 + (gh & 31)) * 32 + (gw & 31);
                cp4_zfill(sx + i * 4, g, ok);
            }
        }
        uint32_t sw = sx + XS_BYTES;
        const float4* gw4 = (const float4*)(g_wflip + cc * 6912);
#pragma unroll
        for (int j = 0; j < 4; ++j) {
            int i = tid + j * 512;
            if (i < 1728) cp16(sw + i * 16, gw4 + i);
        }
        cp_commit();
    };

    // acc[pd][ph][pw][j]: point (2dq+pd, 2hq+ph, 2wq+pw), co pair
    // {4cog+2j, 4cog+2j+1}
    unsigned long long acc[2][2][2][2];
#pragma unroll
    for (int a = 0; a < 2; ++a)
#pragma unroll
    for (int bq = 0; bq < 2; ++bq)
#pragma unroll
    for (int c = 0; c < 2; ++c)
#pragma unroll
    for (int e = 0; e < 2; ++e) acc[a][bq][c][e] = 0ull;

    issue_chunk(0, 0);

#pragma unroll 1
    for (int cc = 0; cc < NCHUNK; ++cc) {
        const int buf = cc & 1;
        if (cc + 1 < NCHUNK) {
            issue_chunk(cc + 1, buf ^ 1);
            cp_wait<1>();
        } else {
            cp_wait<0>();
        }
        __syncthreads();

        const float* xsb = (const float*)(smem + buf * BUF_BYTES);
        const float* wsb = (const float*)(smem + buf * BUF_BYTES + XS_BYTES);

#pragma unroll 1
        for (int ci = 0; ci < CIC; ++ci) {
            // patch base: dd = 2dq, hh = 2hq, ww = 2wq (halo coords)
            const float* xci = xsb + ci * 1000 + dq * 200 + hq * 20 + wq * 2;
            const float* wb  = wsb + ci * 864 + cog * 4;

#pragma unroll
            for (int dz = 0; dz < 4; ++dz) {
                // ---- load one 4x4 halo plane: 8 LDS.64 -> 16 xv2 ----
                unsigned long long xv2[4][4];
#pragma unroll
                for (int hh = 0; hh < 4; ++hh) {
#pragma unroll
                    for (int wp = 0; wp < 2; ++wp) {
                        float2 f = *(const float2*)
                            (xci + dz * 100 + hh * 10 + wp * 2);
                        asm("mov.b64 %0, {%1, %1};"
                            : "=l"(xv2[hh][2 * wp])     : "f"(f.x));
                        asm("mov.b64 %0, {%1, %1};"
                            : "=l"(xv2[hh][2 * wp + 1]) : "f"(f.y));
                    }
                }
                // ---- taps feeding from this plane: pd + kd == dz ----
#pragma unroll
                for (int pd = 0; pd < 2; ++pd) {
                    const int kd = dz - pd;
                    if (kd < 0 || kd > 2) continue;
#pragma unroll
                    for (int kh = 0; kh < 3; ++kh) {
#pragma unroll
                        for (int kw = 0; kw < 3; ++kw) {
                            ulonglong2 wv = *(const ulonglong2*)
                                (wb + (kd * 9 + kh * 3 + kw) * 32);
#pragma unroll
                            for (int ph = 0; ph < 2; ++ph) {
#pragma unroll
                                for (int pw = 0; pw < 2; ++pw) {
                                    unsigned long long xv =
                                        xv2[ph + kh][pw + kw];
                                    asm("fma.rn.f32x2 %0, %1, %2, %0;"
                                        : "+l"(acc[pd][ph][pw][0])
                                        : "l"(xv), "l"(wv.x));
                                    asm("fma.rn.f32x2 %0, %1, %2, %0;"
                                        : "+l"(acc[pd][ph][pw][1])
                                        : "l"(xv), "l"(wv.y));
                                }
                            }
                        }
                    }
                }
            }
        }
        __syncthreads();
    }

    // ---- epilogue: full 2x2x2 output cubes per (point, co) ----
    float bv[4];
#pragma unroll
    for (int j = 0; j < 4; ++j) bv[j] = __ldg(&bias[cog * 4 + j]);

#pragma unroll
    for (int pd = 0; pd < 2; ++pd) {
        const int od = 2 * (zd0 + 2 * dq + pd);
#pragma unroll
        for (int ph = 0; ph < 2; ++ph) {
            const int ohe = 2 * (zh0 + 2 * hq + ph);
#pragma unroll
            for (int pw = 0; pw < 2; ++pw) {
                const int owe = 2 * (zw0 + 2 * wq + pw);
#pragma unroll
                for (int j = 0; j < 2; ++j) {
                    float2 v;
                    asm("mov.b64 {%0, %1}, %2;"
                        : "=f"(v.x), "=f"(v.y) : "l"(acc[pd][ph][pw][j]));
#pragma unroll
                    for (int s = 0; s < 2; ++s) {
                        const int co = cog * 4 + 2 * j + s;
                        const float b  = bv[2 * j + s];
                        const float cr = (s == 0 ? v.x : v.y) + b;
                        float* base = out
                            + (size_t)(n * 32 + co) * CH_STRIDE
                            + (size_t)od * PLANE + ohe * OUT_S + owe;
                        float2 bb = make_float2(b, b);
                        float2 bc = make_float2(b, cr);
                        *(float2*)(base)                 = bb;
                        *(float2*)(base + OUT_S)         = bb;
                        *(float2*)(base + PLANE)         = bb;
                        *(float2*)(base + PLANE + OUT_S) = bc;
                    }
                }
            }
        }
    }
}

// ---------------------------------------------------------------------------
extern "C" void kernel_launch(void* const* d_in, const int* in_sizes, int n_in,
                              void* d_out, int out_size) {
    const float* x = nullptr;
    const float* w = nullptr;
    const float* b = nullptr;
    for (int i = 0; i < n_in; ++i) {
        if (in_sizes[i] == 4194304)    x = (const float*)d_in[i];
        else if (in_sizes[i] == 55296) w = (const float*)d_in[i];
        else if (in_sizes[i] == 32)    b = (const float*)d_in[i];
    }
    float* out = (float*)d_out;

    cudaFuncSetAttribute(conv_core_kernel,
                         cudaFuncAttributeMaxDynamicSharedMemorySize, SM_TOTAL);

    prep_kernel<<<PREP_BLOCKS, 256>>>(w, b, out);

    dim3 grid(4, 4, 8);   // 128 CTAs = one per SM, single wave
    conv_core_kernel<<<grid, 512, SM_TOTAL>>>(x, b, out);
}